// round 12
// baseline (speedup 1.0000x reference)
#include <cuda_runtime.h>
#include <cuda_fp16.h>
#include <cstdint>
#include <cstring>

// Problem constants (fixed-shape problem instance)
#define N_NODES 50000
#define N_EDGES 800000
#define BATCH   2
#define FDIM    128
#define BF      (BATCH * FDIM)   // 256 values per node row in x_lin
#define SLOTS   64               // per-row edge slots (Poisson(16): P(row>64) ~ 1e-19)

// fused-kernel grid: bid%5==0 -> GEMM block, else edge block (1 edge/thread; R8-proven)
#define EDGE_BLOCKS 3125         // 3125*256 = 800000 exact
#define GEMM_BLOCKS 782          // 391 n-tiles x 2 batches
#define FUSED_GRID  (EDGE_BLOCKS + GEMM_BLOCKS)   // 3907

// ---------------- device scratch (no allocations allowed) ----------------
// All state is BSS-zero at load and restored to zero by the consuming kernels,
// so every kernel_launch call sees the identical entry state (no init kernel).
__device__ float g_degsum[N_NODES];   // sum of incident edge weights (deg = 1 + degsum)
__device__ float g_dinv[N_NODES];
__device__ int   g_cursor[N_NODES];
__device__ int2  g_edge[(size_t)N_NODES * SLOTS];   // {col, w bits}
__device__ __half g_xlinh[(size_t)N_NODES * BF];    // [N][B*F] fp16, b-major in row

// ---------------- helpers ----------------
__device__ __forceinline__ unsigned h2u(__half2 h) {
    unsigned u; memcpy(&u, &h, 4); return u;
}
__device__ __forceinline__ __half2 u2h(unsigned u) {
    __half2 h; memcpy(&h, &u, 4); return h;
}
__device__ __forceinline__ unsigned saddr(const void* p) {
    return (unsigned)__cvta_generic_to_shared(p);
}
__device__ __forceinline__ void ldsm4(unsigned* r, unsigned addr) {
    asm volatile("ldmatrix.sync.aligned.m8n8.x4.shared.b16 {%0,%1,%2,%3}, [%4];"
        : "=r"(r[0]), "=r"(r[1]), "=r"(r[2]), "=r"(r[3]) : "r"(addr));
}
__device__ __forceinline__ void mma16816(float* d, const unsigned* a, const unsigned* b) {
    asm volatile("mma.sync.aligned.m16n8k16.row.col.f32.f16.f16.f32 "
        "{%0,%1,%2,%3}, {%4,%5,%6,%7}, {%8,%9}, {%0,%1,%2,%3};"
        : "+f"(d[0]), "+f"(d[1]), "+f"(d[2]), "+f"(d[3])
        : "r"(a[0]), "r"(a[1]), "r"(a[2]), "r"(a[3]), "r"(b[0]), "r"(b[1]));
}

// ---------------- fused kernel: edge-build blocks + HMMA GEMM blocks ----------------
// GEMM: x_lin[n][b*128+o] = sum_k x[b][n][k]*W[o][k] + bias[o], fp16 in/fp32 acc,
// stored fp16. Block tile 128n x 128o, K chunked 2 x 64 in smem. 8 warps as 4m x 2n;
// warp tile 32n x 64o via mma.m16n8k16 (2 m-tiles x 8 n-tiles per k-step of 16).
#define KC 64
__global__ void __launch_bounds__(256, 2) k_fused(const float* __restrict__ x,
                                                  const float* __restrict__ W,
                                                  const float* __restrict__ bias,
                                                  const int* __restrict__ ei,
                                                  const float* __restrict__ ea) {
    __shared__ __align__(16) __half As[128][72];   // node rows x k-chunk (pad 8)
    __shared__ __align__(16) __half Bs[128][72];   // o rows    x k-chunk (pad 8)

    const int bid = blockIdx.x;
    const int tid = threadIdx.x;

    if ((bid % 5) != 0) {
        // ---------------- edge-build block (R8 shape: 1 edge/thread, many blocks) ----
        int edge_id = bid - 1 - bid / 5;            // 0..EDGE_BLOCKS-1
        int e = edge_id * 256 + tid;                // exact: 3125*256 = 800000
        int   r = __ldg(ei + e);
        int   c = __ldg(ei + N_EDGES + e);
        float w = __ldg(ea + e);
        atomicAdd(&g_degsum[r], w);                 // RED (no return)
        int slot = atomicAdd(&g_cursor[r], 1);
        g_edge[(size_t)r * SLOTS + slot] = make_int2(c, __float_as_int(w));
        return;
    }

    // ---------------- GEMM block ----------------
    const int gemm_id = bid / 5;                    // 0..GEMM_BLOCKS-1
    const int n0 = (gemm_id % 391) * 128;
    const int b  = gemm_id / 391;

    const int warp = tid >> 5;
    const int lane = tid & 31;
    const int wm = (warp >> 1) * 32;                // warp m-origin (node rows)
    const int wn = (warp & 1) * 64;                 // warp n-origin (out features)

    float acc[2][8][4];
    #pragma unroll
    for (int mt = 0; mt < 2; mt++)
        #pragma unroll
        for (int nt = 0; nt < 8; nt++)
            #pragma unroll
            for (int q = 0; q < 4; q++) acc[mt][nt][q] = 0.f;

    for (int kc = 0; kc < 2; ++kc) {
        // stage x (fp32 -> fp16) and W chunk; 2048 float4 loads by 256 threads
        #pragma unroll
        for (int t = 0; t < 8; ++t) {
            int i = tid + t * 256;
            int r = i >> 4, q = i & 15;             // r: row 0..127, q: float4 idx
            float4 xv = make_float4(0.f, 0.f, 0.f, 0.f);
            if (n0 + r < N_NODES)
                xv = *(const float4*)(x + ((size_t)b * N_NODES + n0 + r) * FDIM
                                        + kc * KC + q * 4);
            uint2 hx;
            hx.x = h2u(__floats2half2_rn(xv.x, xv.y));
            hx.y = h2u(__floats2half2_rn(xv.z, xv.w));
            *(uint2*)&As[r][q * 4] = hx;

            float4 wv = *(const float4*)(W + (size_t)r * FDIM + kc * KC + q * 4);
            uint2 hw;
            hw.x = h2u(__floats2half2_rn(wv.x, wv.y));
            hw.y = h2u(__floats2half2_rn(wv.z, wv.w));
            *(uint2*)&Bs[r][q * 4] = hw;
        }
        __syncthreads();

        #pragma unroll
        for (int ks = 0; ks < 4; ++ks) {
            const int k0 = ks * 16;
            // A fragments: 2 m-tiles of 16
            unsigned a[2][4];
            #pragma unroll
            for (int mt = 0; mt < 2; mt++) {
                int row = wm + mt * 16 + (lane & 15);
                int col = k0 + (lane >> 4) * 8;
                ldsm4(a[mt], saddr(&As[row][col]));
            }
            // B fragments: 8 n-tiles of 8 (2 per ldmatrix.x4)
            unsigned bf[8][2];
            #pragma unroll
            for (int bt = 0; bt < 4; bt++) {
                int row = wn + bt * 16 + ((lane >> 4) << 3) + (lane & 7);
                int col = k0 + ((lane >> 3) & 1) * 8;
                unsigned tr[4];
                ldsm4(tr, saddr(&Bs[row][col]));
                bf[2 * bt][0] = tr[0];     bf[2 * bt][1] = tr[1];
                bf[2 * bt + 1][0] = tr[2]; bf[2 * bt + 1][1] = tr[3];
            }
            #pragma unroll
            for (int mt = 0; mt < 2; mt++)
                #pragma unroll
                for (int nt = 0; nt < 8; nt++)
                    mma16816(acc[mt][nt], a[mt], bf[nt]);
        }
        __syncthreads();
    }

    // epilogue: add bias, fp16 convert, store to g_xlinh[node][b*128 + o]
    const int g   = lane >> 2;
    const int tig = lane & 3;
    #pragma unroll
    for (int nt = 0; nt < 8; nt++) {
        int o = wn + nt * 8 + 2 * tig;
        float2 bb = *(const float2*)(bias + o);
        #pragma unroll
        for (int mt = 0; mt < 2; mt++) {
            int node0 = n0 + wm + mt * 16 + g;
            int node1 = node0 + 8;
            if (node0 < N_NODES)
                *(unsigned*)&g_xlinh[(size_t)node0 * BF + b * FDIM + o] =
                    h2u(__floats2half2_rn(acc[mt][nt][0] + bb.x,
                                          acc[mt][nt][1] + bb.y));
            if (node1 < N_NODES)
                *(unsigned*)&g_xlinh[(size_t)node1 * BF + b * FDIM + o] =
                    h2u(__floats2half2_rn(acc[mt][nt][2] + bb.x,
                                          acc[mt][nt][3] + bb.y));
        }
    }
}

// ---------------- K_dinv: dinv = rsqrt(1 + degsum), and reset degsum for next call ----------------
__global__ void k_dinv() {
    int i = blockIdx.x * blockDim.x + threadIdx.x;
    if (i < N_NODES) {
        g_dinv[i] = rsqrtf(1.0f + g_degsum[i]);
        g_degsum[i] = 0.f;                     // restore entry invariant
    }
}

// ---------------- K2: aggregation + self loop + ReLU (R8-proven direct-load form) ----
// one warp per destination node; lane covers 8 consecutive halves (16B LDG per edge).
// out_r = dinv_r * ( sum_e w_e*dinv_{c_e}*xl_c + dinv_r*xl_r )
__device__ __forceinline__ void h8_to_f8(uint4 q, float* c) {
    float2 t;
    t = __half22float2(u2h(q.x)); c[0] = t.x; c[1] = t.y;
    t = __half22float2(u2h(q.y)); c[2] = t.x; c[3] = t.y;
    t = __half22float2(u2h(q.z)); c[4] = t.x; c[5] = t.y;
    t = __half22float2(u2h(q.w)); c[6] = t.x; c[7] = t.y;
}

__global__ void __launch_bounds__(256) k_agg(float* __restrict__ out) {
    const int warp = (blockIdx.x * blockDim.x + threadIdx.x) >> 5;
    const int lane = threadIdx.x & 31;
    if (warp >= N_NODES) return;
    const int r = warp;

    const uint4* xl = (const uint4*)g_xlinh;     // 32 uint4 (8 halves each) per row
    const int2*  erow = g_edge + (size_t)r * SLOTS;

    const float dr  = g_dinv[r];
    const int   cnt = g_cursor[r];
    if (lane == 0) g_cursor[r] = 0;              // restore entry invariant

    float a[8];
    {
        float c[8];
        h8_to_f8(__ldg(xl + (size_t)r * 32 + lane), c);
        #pragma unroll
        for (int i = 0; i < 8; i++) a[i] = dr * c[i];   // self-loop (outer dr later)
    }

    int j = 0;
    for (; j + 4 <= cnt; j += 4) {
        int2 e0 = __ldg(erow + j),     e1 = __ldg(erow + j + 1);
        int2 e2 = __ldg(erow + j + 2), e3 = __ldg(erow + j + 3);
        uint4 q0 = __ldg(xl + (size_t)e0.x * 32 + lane);
        uint4 q1 = __ldg(xl + (size_t)e1.x * 32 + lane);
        uint4 q2 = __ldg(xl + (size_t)e2.x * 32 + lane);
        uint4 q3 = __ldg(xl + (size_t)e3.x * 32 + lane);
        float w0 = __int_as_float(e0.y) * __ldg(g_dinv + e0.x);
        float w1 = __int_as_float(e1.y) * __ldg(g_dinv + e1.x);
        float w2 = __int_as_float(e2.y) * __ldg(g_dinv + e2.x);
        float w3 = __int_as_float(e3.y) * __ldg(g_dinv + e3.x);
        float c0[8], c1[8], c2[8], c3[8];
        h8_to_f8(q0, c0); h8_to_f8(q1, c1); h8_to_f8(q2, c2); h8_to_f8(q3, c3);
        #pragma unroll
        for (int i = 0; i < 8; i++) a[i] = fmaf(w0, c0[i], a[i]);
        #pragma unroll
        for (int i = 0; i < 8; i++) a[i] = fmaf(w1, c1[i], a[i]);
        #pragma unroll
        for (int i = 0; i < 8; i++) a[i] = fmaf(w2, c2[i], a[i]);
        #pragma unroll
        for (int i = 0; i < 8; i++) a[i] = fmaf(w3, c3[i], a[i]);
    }
    for (; j < cnt; ++j) {
        int2 e0 = __ldg(erow + j);
        uint4 q0 = __ldg(xl + (size_t)e0.x * 32 + lane);
        float w0 = __int_as_float(e0.y) * __ldg(g_dinv + e0.x);
        float c0[8];
        h8_to_f8(q0, c0);
        #pragma unroll
        for (int i = 0; i < 8; i++) a[i] = fmaf(w0, c0[i], a[i]);
    }

    // outer dinv_r, ReLU, streaming store.
    // lane 0..15 -> batch 0, f = lane*8 ; lane 16..31 -> batch 1, f = (lane-16)*8
    #pragma unroll
    for (int i = 0; i < 8; i++) a[i] = fmaxf(dr * a[i], 0.f);

    float* dst = (lane < 16)
        ? (out + (size_t)r * FDIM + lane * 8)
        : (out + ((size_t)N_NODES + r) * FDIM + (lane - 16) * 8);
    float4 s0 = make_float4(a[0], a[1], a[2], a[3]);
    float4 s1 = make_float4(a[4], a[5], a[6], a[7]);
    __stcs((float4*)dst, s0);
    __stcs((float4*)(dst + 4), s1);
}

// ---------------- launch ----------------
extern "C" void kernel_launch(void* const* d_in, const int* in_sizes, int n_in,
                              void* d_out, int out_size) {
    const float* x    = (const float*)d_in[0];
    const int*   ei   = (const int*)d_in[1];     // int32 (JAX x64 disabled)
    const float* ea   = (const float*)d_in[2];
    const float* W    = (const float*)d_in[3];
    const float* bias = (const float*)d_in[4];
    float* out = (float*)d_out;

    k_fused<<<FUSED_GRID, 256>>>(x, W, bias, ei, ea);
    k_dinv<<<(N_NODES + 255) / 256, 256>>>();
    k_agg<<<(N_NODES + 7) / 8, 256>>>(out);
}

// round 13
// speedup vs baseline: 1.8977x; 1.8977x over previous
#include <cuda_runtime.h>
#include <cuda_fp16.h>
#include <cstdint>
#include <cstring>

// Problem constants (fixed-shape problem instance)
#define N_NODES 50000
#define N_EDGES 800000
#define BATCH   2
#define FDIM    128
#define BF      (BATCH * FDIM)   // 256 values per node row in x_lin
#define SLOTS   64               // per-row edge slots (Poisson(16): P(row>64) ~ 1e-19)

// fused-kernel grid: edge blocks : gemm blocks = 3125 : 782, interleaved 4:1
#define EDGE_BLOCKS 3125
#define GEMM_BLOCKS 782          // 391 n-tiles x 2 batches
#define FUSED_GRID  (EDGE_BLOCKS + GEMM_BLOCKS)   // 3907

// ---------------- device scratch (no allocations allowed) ----------------
__device__ float g_deg[N_NODES];
__device__ float g_dinv[N_NODES];
__device__ int   g_cursor[N_NODES];
__device__ int2  g_edge[(size_t)N_NODES * SLOTS];   // {col, w bits}
__device__ __half g_xlinh[(size_t)N_NODES * BF];    // [N][B*F] fp16, b-major in row

// ---------------- helpers ----------------
__device__ __forceinline__ unsigned h2u(__half2 h) {
    unsigned u; memcpy(&u, &h, 4); return u;
}
__device__ __forceinline__ __half2 u2h(unsigned u) {
    __half2 h; memcpy(&h, &u, 4); return h;
}
__device__ __forceinline__ unsigned saddr(const void* p) {
    return (unsigned)__cvta_generic_to_shared(p);
}
__device__ __forceinline__ void ldsm4(unsigned* r, unsigned addr) {
    asm volatile("ldmatrix.sync.aligned.m8n8.x4.shared.b16 {%0,%1,%2,%3}, [%4];"
        : "=r"(r[0]), "=r"(r[1]), "=r"(r[2]), "=r"(r[3]) : "r"(addr));
}
__device__ __forceinline__ void mma16816(float* d, const unsigned* a, const unsigned* b) {
    asm volatile("mma.sync.aligned.m16n8k16.row.col.f32.f16.f16.f32 "
        "{%0,%1,%2,%3}, {%4,%5,%6,%7}, {%8,%9}, {%0,%1,%2,%3};"
        : "+f"(d[0]), "+f"(d[1]), "+f"(d[2]), "+f"(d[3])
        : "r"(a[0]), "r"(a[1]), "r"(a[2]), "r"(a[3]), "r"(b[0]), "r"(b[1]));
}

// ---------------- K0: init ----------------
__global__ void k_init() {
    int i = blockIdx.x * blockDim.x + threadIdx.x;
    if (i < N_NODES) {
        g_deg[i] = 1.0f;   // self-loop weight
        g_cursor[i] = 0;
    }
}

// ---------------- fused kernel: edge-build blocks + HMMA GEMM blocks ----------------
// GEMM: x_lin[n][b*128+o] = sum_k x[b][n][k]*W[o][k] + bias[o], fp16 in/fp32 acc,
// stored fp16. Block tile 128n x 128o, K chunked 2 x 64 in smem. 8 warps as 4m x 2n;
// warp tile 32n x 64o via mma.m16n8k16 (2 m-tiles x 8 n-tiles per k-step of 16).
#define KC 64
__global__ void __launch_bounds__(256, 2) k_fused(const float* __restrict__ x,
                                                  const float* __restrict__ W,
                                                  const float* __restrict__ bias,
                                                  const int* __restrict__ ei,
                                                  const float* __restrict__ ea) {
    __shared__ __align__(16) __half As[128][72];   // node rows x k-chunk (pad 8)
    __shared__ __align__(16) __half Bs[128][72];   // o rows    x k-chunk (pad 8)

    const int bid = blockIdx.x;
    const int tid = threadIdx.x;

    if ((bid % 5) != 0) {
        // ---------------- edge-build block ----------------
        int edge_id = bid - 1 - bid / 5;            // 0..EDGE_BLOCKS-1
        int e = edge_id * 256 + tid;                // exact: 3125*256 = 800000
        int   r = ei[e];
        int   c = ei[N_EDGES + e];
        float w = ea[e];
        atomicAdd(&g_deg[r], w);
        int slot = atomicAdd(&g_cursor[r], 1);
        g_edge[(size_t)r * SLOTS + slot] = make_int2(c, __float_as_int(w));
        return;
    }

    // ---------------- GEMM block ----------------
    const int gemm_id = bid / 5;                    // 0..GEMM_BLOCKS-1
    const int n0 = (gemm_id % 391) * 128;
    const int b  = gemm_id / 391;

    const int warp = tid >> 5;
    const int lane = tid & 31;
    const int wm = (warp >> 1) * 32;                // warp m-origin (node rows)
    const int wn = (warp & 1) * 64;                 // warp n-origin (out features)

    float acc[2][8][4];
    #pragma unroll
    for (int mt = 0; mt < 2; mt++)
        #pragma unroll
        for (int nt = 0; nt < 8; nt++)
            #pragma unroll
            for (int q = 0; q < 4; q++) acc[mt][nt][q] = 0.f;

    for (int kc = 0; kc < 2; ++kc) {
        // stage x (fp32 -> fp16) and W chunk; 2048 float4 loads by 256 threads
        #pragma unroll
        for (int t = 0; t < 8; ++t) {
            int i = tid + t * 256;
            int r = i >> 4, q = i & 15;             // r: row 0..127, q: float4 idx
            float4 xv = make_float4(0.f, 0.f, 0.f, 0.f);
            if (n0 + r < N_NODES)
                xv = *(const float4*)(x + ((size_t)b * N_NODES + n0 + r) * FDIM
                                        + kc * KC + q * 4);
            uint2 hx;
            hx.x = h2u(__floats2half2_rn(xv.x, xv.y));
            hx.y = h2u(__floats2half2_rn(xv.z, xv.w));
            *(uint2*)&As[r][q * 4] = hx;

            float4 wv = *(const float4*)(W + (size_t)r * FDIM + kc * KC + q * 4);
            uint2 hw;
            hw.x = h2u(__floats2half2_rn(wv.x, wv.y));
            hw.y = h2u(__floats2half2_rn(wv.z, wv.w));
            *(uint2*)&Bs[r][q * 4] = hw;
        }
        __syncthreads();

        #pragma unroll
        for (int ks = 0; ks < 4; ++ks) {
            const int k0 = ks * 16;
            // A fragments: 2 m-tiles of 16
            unsigned a[2][4];
            #pragma unroll
            for (int mt = 0; mt < 2; mt++) {
                int row = wm + mt * 16 + (lane & 15);
                int col = k0 + (lane >> 4) * 8;
                ldsm4(a[mt], saddr(&As[row][col]));
            }
            // B fragments: 8 n-tiles of 8 (2 per ldmatrix.x4)
            unsigned bf[8][2];
            #pragma unroll
            for (int bt = 0; bt < 4; bt++) {
                int row = wn + bt * 16 + ((lane >> 4) << 3) + (lane & 7);
                int col = k0 + ((lane >> 3) & 1) * 8;
                unsigned tr[4];
                ldsm4(tr, saddr(&Bs[row][col]));
                bf[2 * bt][0] = tr[0];     bf[2 * bt][1] = tr[1];
                bf[2 * bt + 1][0] = tr[2]; bf[2 * bt + 1][1] = tr[3];
            }
            #pragma unroll
            for (int mt = 0; mt < 2; mt++)
                #pragma unroll
                for (int nt = 0; nt < 8; nt++)
                    mma16816(acc[mt][nt], a[mt], bf[nt]);
        }
        __syncthreads();
    }

    // epilogue: add bias, fp16 convert, store to g_xlinh[node][b*128 + o]
    const int g   = lane >> 2;
    const int tig = lane & 3;
    #pragma unroll
    for (int nt = 0; nt < 8; nt++) {
        int o = wn + nt * 8 + 2 * tig;
        float2 bb = *(const float2*)(bias + o);
        #pragma unroll
        for (int mt = 0; mt < 2; mt++) {
            int node0 = n0 + wm + mt * 16 + g;
            int node1 = node0 + 8;
            if (node0 < N_NODES)
                *(unsigned*)&g_xlinh[(size_t)node0 * BF + b * FDIM + o] =
                    h2u(__floats2half2_rn(acc[mt][nt][0] + bb.x,
                                          acc[mt][nt][1] + bb.y));
            if (node1 < N_NODES)
                *(unsigned*)&g_xlinh[(size_t)node1 * BF + b * FDIM + o] =
                    h2u(__floats2half2_rn(acc[mt][nt][2] + bb.x,
                                          acc[mt][nt][3] + bb.y));
        }
    }
}

// ---------------- K_dinv: dinv = rsqrt(deg) ----------------
__global__ void k_dinv() {
    int i = blockIdx.x * blockDim.x + threadIdx.x;
    if (i < N_NODES) g_dinv[i] = rsqrtf(g_deg[i]);
}

// ---------------- K2: aggregation + self loop + ReLU ----------------
// one warp per destination node; lane covers 8 consecutive halves (16B LDG per edge).
// out_r = dinv_r * ( sum_e w_e*dinv_{c_e}*xl_c + dinv_r*xl_r )
__device__ __forceinline__ void h8_to_f8(uint4 q, float* c) {
    float2 t;
    t = __half22float2(u2h(q.x)); c[0] = t.x; c[1] = t.y;
    t = __half22float2(u2h(q.y)); c[2] = t.x; c[3] = t.y;
    t = __half22float2(u2h(q.z)); c[4] = t.x; c[5] = t.y;
    t = __half22float2(u2h(q.w)); c[6] = t.x; c[7] = t.y;
}

__global__ void __launch_bounds__(256) k_agg(float* __restrict__ out) {
    const int warp = (blockIdx.x * blockDim.x + threadIdx.x) >> 5;
    const int lane = threadIdx.x & 31;
    if (warp >= N_NODES) return;
    const int r = warp;

    const uint4* xl = (const uint4*)g_xlinh;     // 32 uint4 (8 halves each) per row
    const int2*  erow = g_edge + (size_t)r * SLOTS;

    const float dr  = g_dinv[r];
    const int   cnt = g_cursor[r];

    float a[8];
    {
        float c[8];
        h8_to_f8(xl[(size_t)r * 32 + lane], c);
        #pragma unroll
        for (int i = 0; i < 8; i++) a[i] = dr * c[i];   // self-loop (outer dr later)
    }

    int j = 0;
    for (; j + 4 <= cnt; j += 4) {
        int2 e0 = erow[j], e1 = erow[j + 1], e2 = erow[j + 2], e3 = erow[j + 3];
        uint4 q0 = xl[(size_t)e0.x * 32 + lane];
        uint4 q1 = xl[(size_t)e1.x * 32 + lane];
        uint4 q2 = xl[(size_t)e2.x * 32 + lane];
        uint4 q3 = xl[(size_t)e3.x * 32 + lane];
        float w0 = __int_as_float(e0.y) * g_dinv[e0.x];
        float w1 = __int_as_float(e1.y) * g_dinv[e1.x];
        float w2 = __int_as_float(e2.y) * g_dinv[e2.x];
        float w3 = __int_as_float(e3.y) * g_dinv[e3.x];
        float c0[8], c1[8], c2[8], c3[8];
        h8_to_f8(q0, c0); h8_to_f8(q1, c1); h8_to_f8(q2, c2); h8_to_f8(q3, c3);
        #pragma unroll
        for (int i = 0; i < 8; i++) a[i] = fmaf(w0, c0[i], a[i]);
        #pragma unroll
        for (int i = 0; i < 8; i++) a[i] = fmaf(w1, c1[i], a[i]);
        #pragma unroll
        for (int i = 0; i < 8; i++) a[i] = fmaf(w2, c2[i], a[i]);
        #pragma unroll
        for (int i = 0; i < 8; i++) a[i] = fmaf(w3, c3[i], a[i]);
    }
    for (; j < cnt; ++j) {
        int2 e0 = erow[j];
        uint4 q0 = xl[(size_t)e0.x * 32 + lane];
        float w0 = __int_as_float(e0.y) * g_dinv[e0.x];
        float c0[8];
        h8_to_f8(q0, c0);
        #pragma unroll
        for (int i = 0; i < 8; i++) a[i] = fmaf(w0, c0[i], a[i]);
    }

    // outer dinv_r, ReLU, streaming store.
    // lane 0..15 -> batch 0, f = lane*8 ; lane 16..31 -> batch 1, f = (lane-16)*8
    #pragma unroll
    for (int i = 0; i < 8; i++) a[i] = fmaxf(dr * a[i], 0.f);

    float* dst = (lane < 16)
        ? (out + (size_t)r * FDIM + lane * 8)
        : (out + ((size_t)N_NODES + r) * FDIM + (lane - 16) * 8);
    float4 s0 = make_float4(a[0], a[1], a[2], a[3]);
    float4 s1 = make_float4(a[4], a[5], a[6], a[7]);
    __stcs((float4*)dst, s0);
    __stcs((float4*)(dst + 4), s1);
}

// ---------------- launch ----------------
extern "C" void kernel_launch(void* const* d_in, const int* in_sizes, int n_in,
                              void* d_out, int out_size) {
    const float* x    = (const float*)d_in[0];
    const int*   ei   = (const int*)d_in[1];     // int32 (JAX x64 disabled)
    const float* ea   = (const float*)d_in[2];
    const float* W    = (const float*)d_in[3];
    const float* bias = (const float*)d_in[4];
    float* out = (float*)d_out;

    k_init<<<(N_NODES + 255) / 256, 256>>>();
    k_fused<<<FUSED_GRID, 256>>>(x, W, bias, ei, ea);
    k_dinv<<<(N_NODES + 255) / 256, 256>>>();
    k_agg<<<(N_NODES + 7) / 8, 256>>>(out);
}